// round 11
// baseline (speedup 1.0000x reference)
#include <cuda_runtime.h>
#include <cstdint>

#define NN   32
#define CCH  64
#define HHH  112
#define WWW  112
#define HW   (HHH*WWW)      // 12544
#define OO   64
#define NTILES (NN*HHH)     // 3584
#define GRID 448

// smem layout (dynamic)
#define SMEM_B     0
#define B_BYTES    36864            // 18 kchunks * 8 ntiles * 32 lanes * 8B
#define SMEM_ACT   36864
#define ACT_ROW    8448             // 132 slots * 64B
#define SMEM_STAGE 36864            // overlays act region (sequenced by syncs)
#define STAGE_STRIDE 116            // floats; conflict-free
#define SMEM_TOTAL 66560            // 36864 + 64*116*4

typedef unsigned int uint;

// Device scratch (no allocation)
__device__ __align__(16) signed char g_acts8[(long)NN * HW * CCH];  // 25.7 MB NHWC sign
__device__ __align__(16) uint2       g_wfrag[18 * 8 * 32];          // B frags, mma layout

// ---------------------------------------------------------------------------
// Kernel 1: pack weights directly into m16n8k32 B-fragment layout.
// grid 18 (kc), block 256 (nt*32+lane). b0 bytes j: k=kc*32+tig*4+j; b1: +16.
// ---------------------------------------------------------------------------
__global__ void pack_wfrag(const float* __restrict__ w) {
    int kc   = blockIdx.x;
    int nt   = threadIdx.x >> 5;
    int lane = threadIdx.x & 31;
    int grp  = lane >> 2, tig = lane & 3;
    int ncol = nt * 8 + grp;            // output channel o
    uint b0 = 0, b1 = 0;
#pragma unroll
    for (int j = 0; j < 4; j++) {
        int k0 = kc * 32 + tig * 4 + j;
        int k1 = k0 + 16;
        int t0 = k0 / 64, c0 = k0 % 64;
        int t1 = k1 / 64, c1 = k1 % 64;
        float v0 = w[(ncol * 64 + c0) * 9 + t0];
        float v1 = w[(ncol * 64 + c1) * 9 + t1];
        int s0 = (v0 > 0.f) - (v0 < 0.f);
        int s1 = (v1 > 0.f) - (v1 < 0.f);
        b0 |= (uint)(unsigned char)(signed char)s0 << (8 * j);
        b1 |= (uint)(unsigned char)(signed char)s1 << (8 * j);
    }
    g_wfrag[(kc * 8 + nt) * 32 + lane] = make_uint2(b0, b1);
}

// ---------------------------------------------------------------------------
// Kernel 2: pack activations fp32 NCHW -> s8 sign NHWC.
// grid (112, 32) = (y, n), block 112 (one thread per x).
// ---------------------------------------------------------------------------
__global__ void pack_act(const float* __restrict__ act) {
    int x = threadIdx.x;      // 0..111
    int y = blockIdx.x, n = blockIdx.y;
    const float* base = act + ((long)n * CCH) * HW + y * WWW + x;
    uint wd[16];
#pragma unroll
    for (int j = 0; j < 16; j++) wd[j] = 0;
#pragma unroll
    for (int c = 0; c < CCH; c++) {
        float v = base[(long)c * HW];
        int s = (v > 0.f) - (v < 0.f);
        wd[c >> 2] |= (uint)(unsigned char)(signed char)s << ((c & 3) * 8);
    }
    int4* dst = (int4*)(g_acts8 + ((long)((n * HHH + y) * WWW + x) << 6));
#pragma unroll
    for (int j = 0; j < 4; j++)
        dst[j] = make_int4(wd[4*j], wd[4*j+1], wd[4*j+2], wd[4*j+3]);
}

// ---------------------------------------------------------------------------
// A-fragment smem load with XOR swizzle (chunk' = chunk ^ ((slot>>1)&3)).
// ---------------------------------------------------------------------------
__device__ __forceinline__ uint lda(const char* rowb, int slot, int chunk, int tig) {
    return *(const uint*)(rowb + slot * 64 + ((chunk ^ ((slot >> 1) & 3)) << 4) + tig * 4);
}

// ---------------------------------------------------------------------------
// Kernel 3: implicit-GEMM binary conv via mma.sync m16n8k32 s8s32.
// Persistent: 448 CTAs x 128 threads; tile = (n,y): D[128 xpad, 64 o], K=576.
// ---------------------------------------------------------------------------
__global__ void __launch_bounds__(128, 3) conv_imma(float* __restrict__ out) {
    extern __shared__ char sm[];
    uint2* Bf    = (uint2*)(sm + SMEM_B);
    char*  actsm = sm + SMEM_ACT;
    float* stage = (float*)(sm + SMEM_STAGE);

    int tid = threadIdx.x;
    int warp = tid >> 5, lane = tid & 31, grp = lane >> 2, tig = lane & 3;
    int m0 = warp * 32;

    // Load all B fragments once (36.9 KB)
    for (int i = tid; i < B_BYTES / 16; i += 128)
        ((int4*)Bf)[i] = ((const int4*)g_wfrag)[i];
    __syncthreads();

    for (int tile = blockIdx.x; tile < NTILES; tile += GRID) {
        int n = tile / HHH, y = tile % HHH;

        // Fill 3 act rows (slot = x+1; OOB -> zero), swizzled.
        for (int i = tid; i < 1584; i += 128) {        // 3*132*4 int4
            int r = i / 528, rem = i % 528;
            int slot = rem >> 2, q = rem & 3;
            int yy = y + r - 1, x = slot - 1;
            int4 v = make_int4(0, 0, 0, 0);
            if ((unsigned)yy < HHH && (unsigned)x < WWW)
                v = *(const int4*)(g_acts8 + ((long)((n * HHH + yy) * WWW + x) << 6) + (q << 4));
            *(int4*)(actsm + r * ACT_ROW + slot * 64 + ((q ^ ((slot >> 1) & 3)) << 4)) = v;
        }
        __syncthreads();

        int acc[2][8][4];
#pragma unroll
        for (int mt = 0; mt < 2; mt++)
#pragma unroll
            for (int nt = 0; nt < 8; nt++)
#pragma unroll
                for (int j = 0; j < 4; j++) acc[mt][nt][j] = 0;

#pragma unroll 2
        for (int kc = 0; kc < 18; kc++) {
            int t = kc >> 1, half = kc & 1;
            const char* rowb = actsm + (t / 3) * ACT_ROW;
            int dx = t % 3;
            uint a[2][4];
#pragma unroll
            for (int mt = 0; mt < 2; mt++) {
                int s0 = m0 + mt * 16 + dx + grp;
                a[mt][0] = lda(rowb, s0,     half * 2,     tig);
                a[mt][1] = lda(rowb, s0 + 8, half * 2,     tig);
                a[mt][2] = lda(rowb, s0,     half * 2 + 1, tig);
                a[mt][3] = lda(rowb, s0 + 8, half * 2 + 1, tig);
            }
#pragma unroll
            for (int nt = 0; nt < 8; nt++) {
                uint2 b = Bf[(kc * 8 + nt) * 32 + lane];
#pragma unroll
                for (int mt = 0; mt < 2; mt++) {
                    asm volatile(
                        "mma.sync.aligned.m16n8k32.row.col.s32.s8.s8.s32 "
                        "{%0,%1,%2,%3}, {%4,%5,%6,%7}, {%8,%9}, {%0,%1,%2,%3};"
                        : "+r"(acc[mt][nt][0]), "+r"(acc[mt][nt][1]),
                          "+r"(acc[mt][nt][2]), "+r"(acc[mt][nt][3])
                        : "r"(a[mt][0]), "r"(a[mt][1]), "r"(a[mt][2]), "r"(a[mt][3]),
                          "r"(b.x), "r"(b.y));
                }
            }
        }
        __syncthreads();   // done reading act; stage overlays it

        // Stage results [o][x] as float. Magic conversion with +1024 bias so the
        // argument stays in [448,1600] (nonnegative, exact): FIXES negative-acc bug.
#pragma unroll
        for (int mt = 0; mt < 2; mt++) {
#pragma unroll
            for (int nt = 0; nt < 8; nt++) {
                int o  = nt * 8 + tig * 2;
                int x0 = m0 + mt * 16 + grp;
                int x1 = x0 + 8;
                if (x0 < WWW) {
                    stage[o * STAGE_STRIDE + x0]       = __int_as_float(0x4B000000 + 1024 + acc[mt][nt][0]) - 8389632.f;
                    stage[(o + 1) * STAGE_STRIDE + x0] = __int_as_float(0x4B000000 + 1024 + acc[mt][nt][1]) - 8389632.f;
                }
                if (x1 < WWW) {
                    stage[o * STAGE_STRIDE + x1]       = __int_as_float(0x4B000000 + 1024 + acc[mt][nt][2]) - 8389632.f;
                    stage[(o + 1) * STAGE_STRIDE + x1] = __int_as_float(0x4B000000 + 1024 + acc[mt][nt][3]) - 8389632.f;
                }
            }
        }
        __syncthreads();

        // Coalesced float4 stores: 64 o-rows x 112 floats
        float* ob = out + ((long)(n * OO)) * HW + y * WWW;
        for (int i = tid; i < OO * 28; i += 128) {
            int o = i / 28, qd = i % 28;
            float4 v = *(float4*)(stage + o * STAGE_STRIDE + qd * 4);
            *(float4*)(ob + (long)o * HW + qd * 4) = v;
        }
        __syncthreads();   // stage free before next tile's act fill
    }
}

// ---------------------------------------------------------------------------
extern "C" void kernel_launch(void* const* d_in, const int* in_sizes, int n_in,
                              void* d_out, int out_size) {
    const float* act = (const float*)d_in[0];   // [32,64,112,112]
    const float* w   = (const float*)d_in[1];   // [64*64*9, 1]
    float* out       = (float*)d_out;           // [32,64,112,112]

    cudaFuncSetAttribute(conv_imma,
                         cudaFuncAttributeMaxDynamicSharedMemorySize, SMEM_TOTAL);

    pack_wfrag<<<18, 256>>>(w);
    pack_act<<<dim3(HHH, NN), WWW>>>(act);
    conv_imma<<<GRID, 128, SMEM_TOTAL>>>(out);
}

// round 12
// speedup vs baseline: 2.4978x; 2.4978x over previous
#include <cuda_runtime.h>
#include <cstdint>

#define NN   32
#define CC   64
#define HH   112
#define WW   112
#define HW   (HH*WW)        // 12544
#define OO   64
#define TAPS 9
#define WSTRIDE 10          // padded weight row (16B-aligned rows: 80 bytes)

typedef unsigned long long u64;

// Static device scratch (no allocation)
__device__ __align__(16) u64 g_packed[NN * HW];        // bit c = (A[n][c][y][x] > 0)
__device__ __align__(16) u64 g_wbits[OO * WSTRIDE];    // padded rows of 10
__device__ float             g_fixf[16 * OO];          // per edge-class per o correction

// Full adder (carry-save) — r7-proven form
__device__ __forceinline__ void csa(u64& s, u64& c, u64 x, u64 y, u64 z) {
    u64 u = x ^ y;
    s = u ^ z;
    c = (x & y) | (u & z);
}

// ---------------------------------------------------------------------------
// Kernel 1: pack weights. One warp per (o,t); lane covers channels lane, lane+32.
// ---------------------------------------------------------------------------
__global__ void pack_weights_kernel(const float* __restrict__ w) {
    int wid  = blockIdx.x * (blockDim.x >> 5) + (threadIdx.x >> 5);
    int lane = threadIdx.x & 31;
    if (wid >= OO * TAPS) return;
    int o = wid / TAPS, t = wid % TAPS;
    float v0 = w[(o * CC + lane) * TAPS + t];
    float v1 = w[(o * CC + lane + 32) * TAPS + t];
    unsigned b0 = __ballot_sync(0xFFFFFFFFu, v0 > 0.0f);
    unsigned b1 = __ballot_sync(0xFFFFFFFFu, v1 > 0.0f);
    if (lane == 0)
        g_wbits[o * WSTRIDE + t] = (u64)b0 | ((u64)b1 << 32);
}

// ---------------------------------------------------------------------------
// Kernel 1b: border fix table (float). m: bit0 y==0, bit1 y==111, bit2 x==0,
// bit3 x==111. fix = 2*sum_{invalid taps} popc(w) - 64*n_missing
// ---------------------------------------------------------------------------
__global__ void pack_fix_kernel() {
    int m = blockIdx.x;     // 0..15
    int o = threadIdx.x;    // 0..63
    bool T = m & 1, B = m & 2, L = m & 4, R = m & 8;
    int corr = 0, nmiss = 0;
#pragma unroll
    for (int t = 0; t < 9; t++) {
        int r = t / 3, c = t % 3;
        bool inv = (T && r == 0) || (B && r == 2) || (L && c == 0) || (R && c == 2);
        if (inv) {
            corr += __popcll(g_wbits[o * WSTRIDE + t]);
            nmiss++;
        }
    }
    g_fixf[m * OO + o] = (float)(2 * corr - CC * nmiss);
}

// ---------------------------------------------------------------------------
// Kernel 2: pack activations. 4 consecutive pixels/thread via float4 loads.
// ---------------------------------------------------------------------------
__global__ void pack_act_kernel(const float* __restrict__ act) {
    int tidg = blockIdx.x * blockDim.x + threadIdx.x;
    int p0   = tidg * 4;
    int n    = p0 / HW;
    int p    = p0 - n * HW;

    const float* base = act + (long)(n * CC) * HW + p;
    u64 w0 = 0, w1 = 0, w2 = 0, w3 = 0;
#pragma unroll
    for (int c = 0; c < CC; c++) {
        float4 v = *(const float4*)(base + (long)c * HW);
        w0 |= (u64)(v.x > 0.0f) << c;
        w1 |= (u64)(v.y > 0.0f) << c;
        w2 |= (u64)(v.z > 0.0f) << c;
        w3 |= (u64)(v.w > 0.0f) << c;
    }
    ulonglong2* dst = (ulonglong2*)(g_packed + p0);
    dst[0] = make_ulonglong2(w0, w1);
    dst[1] = make_ulonglong2(w2, w3);
}

// ---------------------------------------------------------------------------
// Kernel 3: binary conv, 4-CSA popcount, fused border, ALL 64 o per block.
// Flat block of 224 (7 full warps): xq = tid%28 -> x0 = xq*4; yo = tid/28.
// grid (14, 32): 8 rows per block, n = blockIdx.y.
// ---------------------------------------------------------------------------
__global__ __launch_bounds__(224)
void bconv_kernel(float* __restrict__ out) {
    __shared__ __align__(16) u64 ws[OO * WSTRIDE];
    __shared__ float fix_s[16 * OO];

    int tid = threadIdx.x;
    for (int i = tid; i < OO * WSTRIDE; i += 224)
        ws[i] = g_wbits[i];
    for (int i = tid; i < 16 * OO; i += 224)
        fix_s[i] = g_fixf[i];
    __syncthreads();

    int xq = tid % 28;
    int x0 = xq * 4;
    int y  = blockIdx.x * 8 + tid / 28;
    int n  = blockIdx.y;

    const u64* pb = g_packed + (long)n * HW;

    // 3x6 window, zero for OOB (corrected via fix table)
    u64 a[3][6];
#pragma unroll
    for (int r = 0; r < 3; r++) {
        int yy = y - 1 + r;
        bool rv = (unsigned)yy < (unsigned)HH;
        const u64* row = pb + yy * WW;
#pragma unroll
        for (int c = 0; c < 6; c++) {
            int xx = x0 - 1 + c;
            bool v = rv && ((unsigned)xx < (unsigned)WW);
            a[r][c] = v ? row[xx] : 0ull;
        }
    }

    // Border class masks (per output pixel)
    int m_y = (y == 0 ? 1 : 0) | (y == 111 ? 2 : 0);
    int m0  = m_y | (x0 == 0 ? 4 : 0);
    int m3  = m_y | (x0 == 108 ? 8 : 0);
    bool anyb = (m0 | m3) != 0;

    const float MAGIC_SUB = 16777792.0f;  // 2^24 + 576

    float* ob = out + ((long)(n * OO)) * HW + y * WW + x0;

#pragma unroll 2
    for (int o = 0; o < OO; o++) {
        const ulonglong2* wr2 = (const ulonglong2*)(ws + o * WSTRIDE);
        ulonglong2 wp0 = wr2[0], wp1 = wr2[1], wp2 = wr2[2], wp3 = wr2[3];
        u64 wv[9] = { wp0.x, wp0.y, wp1.x, wp1.y, wp2.x, wp2.y, wp3.x, wp3.y,
                      ws[o * WSTRIDE + 8] };

        float4 res;
#pragma unroll
        for (int px = 0; px < 4; px++) {
            u64 s0, s1, s2, s3, c0, c1, c2, c3;
            csa(s0, c0, a[0][px] ^ wv[0], a[0][px + 1] ^ wv[1], a[0][px + 2] ^ wv[2]);
            csa(s1, c1, a[1][px] ^ wv[3], a[1][px + 1] ^ wv[4], a[1][px + 2] ^ wv[5]);
            csa(s2, c2, a[2][px] ^ wv[6], a[2][px + 1] ^ wv[7], a[2][px + 2] ^ wv[8]);
            csa(s3, c3, c0, c1, c2);

            int acc = __popcll(s0) + __popcll(s1) + __popcll(s2)
                    + 2 * __popcll(s3) + 4 * __popcll(c3);
            float v = fmaf(-2.0f, __int_as_float(0x4B000000 | acc), MAGIC_SUB);
            if (px == 0) res.x = v;
            else if (px == 1) res.y = v;
            else if (px == 2) res.z = v;
            else res.w = v;
        }

        if (anyb) {
            res.x += fix_s[m0  * OO + o];
            res.y += fix_s[m_y * OO + o];
            res.z += fix_s[m_y * OO + o];
            res.w += fix_s[m3  * OO + o];
        }

        *(float4*)(ob + (long)o * HW) = res;
    }
}

// ---------------------------------------------------------------------------
extern "C" void kernel_launch(void* const* d_in, const int* in_sizes, int n_in,
                              void* d_out, int out_size) {
    const float* act = (const float*)d_in[0];   // [32,64,112,112]
    const float* w   = (const float*)d_in[1];   // [64*64*9, 1]
    float* out       = (float*)d_out;           // [32,64,112,112]

    pack_weights_kernel<<<72, 256>>>(w);
    pack_fix_kernel<<<16, OO>>>();

    pack_act_kernel<<<(NN * HW / 4) / 128, 128>>>(act);

    dim3 grid(HH / 8, NN);
    bconv_kernel<<<grid, 224>>>(out);
}

// round 13
// speedup vs baseline: 2.6523x; 1.0618x over previous
#include <cuda_runtime.h>
#include <cstdint>

#define NN   32
#define CC   64
#define HH   112
#define WW   112
#define HW   (HH*WW)        // 12544
#define OO   64
#define TAPS 9
#define WSTRIDE 10          // padded weight row (16B-aligned rows: 80 bytes)
#define OB   32             // output channels per block

typedef unsigned long long u64;

// Static device scratch (no allocation)
__device__ __align__(16) u64 g_packed[NN * HW];        // bit c = (A[n][c][y][x] > 0)
__device__ __align__(16) u64 g_wbits[OO * WSTRIDE];    // padded rows of 10
__device__ float             g_fixf[16 * OO];          // per edge-class per o correction

// Full adder (carry-save) — r7-proven form
__device__ __forceinline__ void csa(u64& s, u64& c, u64 x, u64 y, u64 z) {
    u64 u = x ^ y;
    s = u ^ z;
    c = (x & y) | (u & z);
}

// ---------------------------------------------------------------------------
// Kernel 1: pack weights. One warp per (o,t); lane covers channels lane, lane+32.
// ---------------------------------------------------------------------------
__global__ void pack_weights_kernel(const float* __restrict__ w) {
    int wid  = blockIdx.x * (blockDim.x >> 5) + (threadIdx.x >> 5);
    int lane = threadIdx.x & 31;
    if (wid >= OO * TAPS) return;
    int o = wid / TAPS, t = wid % TAPS;
    float v0 = w[(o * CC + lane) * TAPS + t];
    float v1 = w[(o * CC + lane + 32) * TAPS + t];
    unsigned b0 = __ballot_sync(0xFFFFFFFFu, v0 > 0.0f);
    unsigned b1 = __ballot_sync(0xFFFFFFFFu, v1 > 0.0f);
    if (lane == 0)
        g_wbits[o * WSTRIDE + t] = (u64)b0 | ((u64)b1 << 32);
}

// ---------------------------------------------------------------------------
// Kernel 1b: border fix table (float). m: bit0 y==0, bit1 y==111, bit2 x==0,
// bit3 x==111. fix = 2*sum_{invalid taps} popc(w) - 64*n_missing
// ---------------------------------------------------------------------------
__global__ void pack_fix_kernel() {
    int m = blockIdx.x;     // 0..15
    int o = threadIdx.x;    // 0..63
    bool T = m & 1, B = m & 2, L = m & 4, R = m & 8;
    int corr = 0, nmiss = 0;
#pragma unroll
    for (int t = 0; t < 9; t++) {
        int r = t / 3, c = t % 3;
        bool inv = (T && r == 0) || (B && r == 2) || (L && c == 0) || (R && c == 2);
        if (inv) {
            corr += __popcll(g_wbits[o * WSTRIDE + t]);
            nmiss++;
        }
    }
    g_fixf[m * OO + o] = (float)(2 * corr - CC * nmiss);
}

// ---------------------------------------------------------------------------
// Kernel 2: pack activations. 4 consecutive pixels/thread via float4 loads.
// ---------------------------------------------------------------------------
__global__ void pack_act_kernel(const float* __restrict__ act) {
    int tidg = blockIdx.x * blockDim.x + threadIdx.x;
    int p0   = tidg * 4;
    int n    = p0 / HW;
    int p    = p0 - n * HW;

    const float* base = act + (long)(n * CC) * HW + p;
    u64 w0 = 0, w1 = 0, w2 = 0, w3 = 0;
#pragma unroll
    for (int c = 0; c < CC; c++) {
        float4 v = *(const float4*)(base + (long)c * HW);
        w0 |= (u64)(v.x > 0.0f) << c;
        w1 |= (u64)(v.y > 0.0f) << c;
        w2 |= (u64)(v.z > 0.0f) << c;
        w3 |= (u64)(v.w > 0.0f) << c;
    }
    ulonglong2* dst = (ulonglong2*)(g_packed + p0);
    dst[0] = make_ulonglong2(w0, w1);
    dst[1] = make_ulonglong2(w2, w3);
}

// ---------------------------------------------------------------------------
// Kernel 3: binary conv, 4-CSA popcount, fused border.
// Flat block 224 (7 full warps): xq = tid%28 -> x0 = xq*4; y = bIdx.x*8 + tid/28.
// OB=32 o's per block; grid (14, 32, 2). launch_bounds(224,4) pins 4 blocks/SM.
// ---------------------------------------------------------------------------
__global__ __launch_bounds__(224, 4)
void bconv_kernel(float* __restrict__ out) {
    __shared__ __align__(16) u64 ws[OB * WSTRIDE];
    __shared__ float fix_s[16 * OB];

    int obase = blockIdx.z * OB;
    int tid = threadIdx.x;
    for (int i = tid; i < OB * WSTRIDE; i += 224)
        ws[i] = g_wbits[obase * WSTRIDE + i];
    for (int i = tid; i < 16 * OB; i += 224)
        fix_s[i] = g_fixf[(i / OB) * OO + obase + (i % OB)];
    __syncthreads();

    int xq = tid % 28;
    int x0 = xq * 4;
    int y  = blockIdx.x * 8 + tid / 28;
    int n  = blockIdx.y;

    const u64* pb = g_packed + (long)n * HW;

    // 3x6 window, zero for OOB (corrected via fix table)
    u64 a[3][6];
#pragma unroll
    for (int r = 0; r < 3; r++) {
        int yy = y - 1 + r;
        bool rv = (unsigned)yy < (unsigned)HH;
        const u64* row = pb + yy * WW;
#pragma unroll
        for (int c = 0; c < 6; c++) {
            int xx = x0 - 1 + c;
            bool v = rv && ((unsigned)xx < (unsigned)WW);
            a[r][c] = v ? row[xx] : 0ull;
        }
    }

    // Border class masks (per output pixel)
    int m_y = (y == 0 ? 1 : 0) | (y == 111 ? 2 : 0);
    int m0  = m_y | (x0 == 0 ? 4 : 0);
    int m3  = m_y | (x0 == 108 ? 8 : 0);
    bool anyb = (m0 | m3) != 0;

    const float MAGIC_SUB = 16777792.0f;  // 2^24 + 576

    float* ob = out + ((long)(n * OO + obase)) * HW + y * WW + x0;

#pragma unroll 2
    for (int o = 0; o < OB; o++) {
        const ulonglong2* wr2 = (const ulonglong2*)(ws + o * WSTRIDE);
        ulonglong2 wp0 = wr2[0], wp1 = wr2[1], wp2 = wr2[2], wp3 = wr2[3];
        u64 wv[9] = { wp0.x, wp0.y, wp1.x, wp1.y, wp2.x, wp2.y, wp3.x, wp3.y,
                      ws[o * WSTRIDE + 8] };

        float4 res;
#pragma unroll
        for (int px = 0; px < 4; px++) {
            u64 s0, s1, s2, s3, c0, c1, c2, c3;
            csa(s0, c0, a[0][px] ^ wv[0], a[0][px + 1] ^ wv[1], a[0][px + 2] ^ wv[2]);
            csa(s1, c1, a[1][px] ^ wv[3], a[1][px + 1] ^ wv[4], a[1][px + 2] ^ wv[5]);
            csa(s2, c2, a[2][px] ^ wv[6], a[2][px + 1] ^ wv[7], a[2][px + 2] ^ wv[8]);
            csa(s3, c3, c0, c1, c2);

            int acc = __popcll(s0) + __popcll(s1) + __popcll(s2)
                    + 2 * __popcll(s3) + 4 * __popcll(c3);
            float v = fmaf(-2.0f, __int_as_float(0x4B000000 | acc), MAGIC_SUB);
            if (px == 0) res.x = v;
            else if (px == 1) res.y = v;
            else if (px == 2) res.z = v;
            else res.w = v;
        }

        if (anyb) {
            res.x += fix_s[m0  * OB + o];
            res.y += fix_s[m_y * OB + o];
            res.z += fix_s[m_y * OB + o];
            res.w += fix_s[m3  * OB + o];
        }

        *(float4*)(ob + (long)o * HW) = res;
    }
}

// ---------------------------------------------------------------------------
extern "C" void kernel_launch(void* const* d_in, const int* in_sizes, int n_in,
                              void* d_out, int out_size) {
    const float* act = (const float*)d_in[0];   // [32,64,112,112]
    const float* w   = (const float*)d_in[1];   // [64*64*9, 1]
    float* out       = (float*)d_out;           // [32,64,112,112]

    pack_weights_kernel<<<72, 256>>>(w);
    pack_fix_kernel<<<16, OO>>>();

    pack_act_kernel<<<(NN * HW / 4) / 128, 128>>>(act);

    dim3 grid(HH / 8, NN, 2);
    bconv_kernel<<<grid, 224>>>(out);
}

// round 14
// speedup vs baseline: 2.8375x; 1.0698x over previous
#include <cuda_runtime.h>
#include <cstdint>

#define NN   32
#define CC   64
#define HH   112
#define WW   112
#define HW   (HH*WW)        // 12544
#define OO   64
#define TAPS 9
#define WSTRIDE 10          // padded weight row (16B-aligned rows: 80 bytes)
#define OB   32             // output channels per block

typedef unsigned long long u64;
typedef unsigned int uint;

// Static device scratch (no allocation)
__device__ __align__(16) u64 g_packed[NN * HW];        // bit c = (A[n][c][y][x] > 0)
__device__ __align__(16) u64 g_wbits[OO * WSTRIDE];    // padded rows of 10
__device__ float             g_fixf[16 * OO];          // per edge-class per o correction

// Carry-save adder with FORCED instruction selection:
// s = XOR3 (lop3 0x96), c = MAJ3 (lop3 0xE8) — exactly 4 LOP3.32 per u64.
__device__ __forceinline__ void csa(u64& s, u64& c, u64 x, u64 y, u64 z) {
    uint xl = (uint)x, xh = (uint)(x >> 32);
    uint yl = (uint)y, yh = (uint)(y >> 32);
    uint zl = (uint)z, zh = (uint)(z >> 32);
    uint sl, sh, cl, ch;
    asm("lop3.b32 %0, %1, %2, %3, 0x96;" : "=r"(sl) : "r"(xl), "r"(yl), "r"(zl));
    asm("lop3.b32 %0, %1, %2, %3, 0x96;" : "=r"(sh) : "r"(xh), "r"(yh), "r"(zh));
    asm("lop3.b32 %0, %1, %2, %3, 0xE8;" : "=r"(cl) : "r"(xl), "r"(yl), "r"(zl));
    asm("lop3.b32 %0, %1, %2, %3, 0xE8;" : "=r"(ch) : "r"(xh), "r"(yh), "r"(zh));
    s = (u64)sl | ((u64)sh << 32);
    c = (u64)cl | ((u64)ch << 32);
}

// ---------------------------------------------------------------------------
// Kernel 1: pack weights. One warp per (o,t); lane covers channels lane, lane+32.
// ---------------------------------------------------------------------------
__global__ void pack_weights_kernel(const float* __restrict__ w) {
    int wid  = blockIdx.x * (blockDim.x >> 5) + (threadIdx.x >> 5);
    int lane = threadIdx.x & 31;
    if (wid >= OO * TAPS) return;
    int o = wid / TAPS, t = wid % TAPS;
    float v0 = w[(o * CC + lane) * TAPS + t];
    float v1 = w[(o * CC + lane + 32) * TAPS + t];
    unsigned b0 = __ballot_sync(0xFFFFFFFFu, v0 > 0.0f);
    unsigned b1 = __ballot_sync(0xFFFFFFFFu, v1 > 0.0f);
    if (lane == 0)
        g_wbits[o * WSTRIDE + t] = (u64)b0 | ((u64)b1 << 32);
}

// ---------------------------------------------------------------------------
// Kernel 1b: border fix table (float). m: bit0 y==0, bit1 y==111, bit2 x==0,
// bit3 x==111. fix = 2*sum_{invalid taps} popc(w) - 64*n_missing
// ---------------------------------------------------------------------------
__global__ void pack_fix_kernel() {
    int m = blockIdx.x;     // 0..15
    int o = threadIdx.x;    // 0..63
    bool T = m & 1, B = m & 2, L = m & 4, R = m & 8;
    int corr = 0, nmiss = 0;
#pragma unroll
    for (int t = 0; t < 9; t++) {
        int r = t / 3, c = t % 3;
        bool inv = (T && r == 0) || (B && r == 2) || (L && c == 0) || (R && c == 2);
        if (inv) {
            corr += __popcll(g_wbits[o * WSTRIDE + t]);
            nmiss++;
        }
    }
    g_fixf[m * OO + o] = (float)(2 * corr - CC * nmiss);
}

// ---------------------------------------------------------------------------
// Kernel 2: pack activations. 4 consecutive pixels/thread via float4 loads.
// ---------------------------------------------------------------------------
__global__ void pack_act_kernel(const float* __restrict__ act) {
    int tidg = blockIdx.x * blockDim.x + threadIdx.x;
    int p0   = tidg * 4;
    int n    = p0 / HW;
    int p    = p0 - n * HW;

    const float* base = act + (long)(n * CC) * HW + p;
    u64 w0 = 0, w1 = 0, w2 = 0, w3 = 0;
#pragma unroll
    for (int c = 0; c < CC; c++) {
        float4 v = *(const float4*)(base + (long)c * HW);
        w0 |= (u64)(v.x > 0.0f) << c;
        w1 |= (u64)(v.y > 0.0f) << c;
        w2 |= (u64)(v.z > 0.0f) << c;
        w3 |= (u64)(v.w > 0.0f) << c;
    }
    ulonglong2* dst = (ulonglong2*)(g_packed + p0);
    dst[0] = make_ulonglong2(w0, w1);
    dst[1] = make_ulonglong2(w2, w3);
}

// ---------------------------------------------------------------------------
// Kernel 3: binary conv, 4-CSA popcount (forced LOP3 XOR3/MAJ3), fused border.
// Flat block 224 (7 full warps); OB=32; grid (14, 32, 2); 4 blocks/SM.
// ---------------------------------------------------------------------------
__global__ __launch_bounds__(224, 4)
void bconv_kernel(float* __restrict__ out) {
    __shared__ __align__(16) u64 ws[OB * WSTRIDE];
    __shared__ float fix_s[16 * OB];

    int obase = blockIdx.z * OB;
    int tid = threadIdx.x;
    for (int i = tid; i < OB * WSTRIDE; i += 224)
        ws[i] = g_wbits[obase * WSTRIDE + i];
    for (int i = tid; i < 16 * OB; i += 224)
        fix_s[i] = g_fixf[(i / OB) * OO + obase + (i % OB)];
    __syncthreads();

    int xq = tid % 28;
    int x0 = xq * 4;
    int y  = blockIdx.x * 8 + tid / 28;
    int n  = blockIdx.y;

    const u64* pb = g_packed + (long)n * HW;

    // 3x6 window, zero for OOB (corrected via fix table)
    u64 a[3][6];
#pragma unroll
    for (int r = 0; r < 3; r++) {
        int yy = y - 1 + r;
        bool rv = (unsigned)yy < (unsigned)HH;
        const u64* row = pb + yy * WW;
#pragma unroll
        for (int c = 0; c < 6; c++) {
            int xx = x0 - 1 + c;
            bool v = rv && ((unsigned)xx < (unsigned)WW);
            a[r][c] = v ? row[xx] : 0ull;
        }
    }

    // Border class masks (per output pixel)
    int m_y = (y == 0 ? 1 : 0) | (y == 111 ? 2 : 0);
    int m0  = m_y | (x0 == 0 ? 4 : 0);
    int m3  = m_y | (x0 == 108 ? 8 : 0);
    bool anyb = (m0 | m3) != 0;

    const float MAGIC_SUB = 16777792.0f;  // 2^24 + 576

    float* ob = out + ((long)(n * OO + obase)) * HW + y * WW + x0;

#pragma unroll 2
    for (int o = 0; o < OB; o++) {
        const ulonglong2* wr2 = (const ulonglong2*)(ws + o * WSTRIDE);
        ulonglong2 wp0 = wr2[0], wp1 = wr2[1], wp2 = wr2[2], wp3 = wr2[3];
        u64 wv[9] = { wp0.x, wp0.y, wp1.x, wp1.y, wp2.x, wp2.y, wp3.x, wp3.y,
                      ws[o * WSTRIDE + 8] };

        float4 res;
#pragma unroll
        for (int px = 0; px < 4; px++) {
            u64 s0, s1, s2, s3, c0, c1, c2, c3;
            csa(s0, c0, a[0][px] ^ wv[0], a[0][px + 1] ^ wv[1], a[0][px + 2] ^ wv[2]);
            csa(s1, c1, a[1][px] ^ wv[3], a[1][px + 1] ^ wv[4], a[1][px + 2] ^ wv[5]);
            csa(s2, c2, a[2][px] ^ wv[6], a[2][px + 1] ^ wv[7], a[2][px + 2] ^ wv[8]);
            csa(s3, c3, c0, c1, c2);

            int acc = __popcll(s0) + __popcll(s1) + __popcll(s2)
                    + 2 * __popcll(s3) + 4 * __popcll(c3);
            float v = fmaf(-2.0f, __int_as_float(0x4B000000 | acc), MAGIC_SUB);
            if (px == 0) res.x = v;
            else if (px == 1) res.y = v;
            else if (px == 2) res.z = v;
            else res.w = v;
        }

        if (anyb) {
            res.x += fix_s[m0  * OB + o];
            res.y += fix_s[m_y * OB + o];
            res.z += fix_s[m_y * OB + o];
            res.w += fix_s[m3  * OB + o];
        }

        *(float4*)(ob + (long)o * HW) = res;
    }
}

// ---------------------------------------------------------------------------
extern "C" void kernel_launch(void* const* d_in, const int* in_sizes, int n_in,
                              void* d_out, int out_size) {
    const float* act = (const float*)d_in[0];   // [32,64,112,112]
    const float* w   = (const float*)d_in[1];   // [64*64*9, 1]
    float* out       = (float*)d_out;           // [32,64,112,112]

    pack_weights_kernel<<<72, 256>>>(w);
    pack_fix_kernel<<<16, OO>>>();

    pack_act_kernel<<<(NN * HW / 4) / 128, 128>>>(act);

    dim3 grid(HH / 8, NN, 2);
    bconv_kernel<<<grid, 224>>>(out);
}